// round 13
// baseline (speedup 1.0000x reference)
#include <cuda_runtime.h>
#include <cuda_fp16.h>
#include <cstdint>
#include <cmath>

#define B_ 64
#define S_ 512
#define D_ 1024
#define H_ 1024
#define G_ 4096
#define RBLK 64               // recurrence CTAs (64 x 512 threads)

// ---------------- scratch (device globals) ----------------
__device__ float g_xw[(size_t)S_ * G_ * B_];    // [t][n'(perm)][b] fp32
__device__ __half g_xh[(size_t)B_ * S_ * D_];   // x fp16
__device__ __half g_Wh[(size_t)G_ * D_];        // W^T perm [n'][k] fp16
__device__ __half g_Uh[(size_t)G_ * H_];        // U^T perm [n'][k] fp16
__device__ __half g_hh[2][B_ * H_];             // h fp16 [b][j], dbl buf
__device__ unsigned g_flag[RBLK * 16];          // per-CTA monotonic step flags (64B stride)

// ---------------- helpers ----------------
__device__ __forceinline__ uint32_t smem_u32(const void* p) {
    uint32_t a;
    asm("{ .reg .u64 t; cvta.to.shared.u64 t, %1; cvt.u32.u64 %0, t; }" : "=r"(a) : "l"(p));
    return a;
}
__device__ __forceinline__ void ldm_x4(uint32_t* r, uint32_t a) {
    asm volatile("ldmatrix.sync.aligned.m8n8.x4.shared.b16 {%0,%1,%2,%3}, [%4];"
                 : "=r"(r[0]), "=r"(r[1]), "=r"(r[2]), "=r"(r[3]) : "r"(a));
}
__device__ __forceinline__ void ldm_x2(uint32_t* r, uint32_t a) {
    asm volatile("ldmatrix.sync.aligned.m8n8.x2.shared.b16 {%0,%1}, [%2];"
                 : "=r"(r[0]), "=r"(r[1]) : "r"(a));
}
__device__ __forceinline__ void mma16816(float* d, const uint32_t* a, const uint32_t* b) {
    asm volatile("mma.sync.aligned.m16n8k16.row.col.f32.f16.f16.f32 "
                 "{%0,%1,%2,%3},{%4,%5,%6,%7},{%8,%9},{%0,%1,%2,%3};"
                 : "+f"(d[0]), "+f"(d[1]), "+f"(d[2]), "+f"(d[3])
                 : "r"(a[0]), "r"(a[1]), "r"(a[2]), "r"(a[3]), "r"(b[0]), "r"(b[1]));
}
__device__ __forceinline__ void cpa16(uint32_t dst, const void* src) {
    asm volatile("cp.async.cg.shared.global [%0], [%1], 16;" :: "r"(dst), "l"(src));
}
#define CP_COMMIT() asm volatile("cp.async.commit_group;" ::: "memory")
#define CP_WAITN(n) asm volatile("cp.async.wait_group %0;" :: "n"(n) : "memory")
__device__ __forceinline__ float fsig(float x) {
    return __fdividef(1.f, 1.f + __expf(-x));
}
__device__ __forceinline__ float ftanh(float x) {
    x = fminf(fmaxf(x, -15.f), 15.f);
    float e = __expf(2.f * x);
    return __fdividef(e - 1.f, e + 1.f);
}

// ---------------- x: fp32 -> fp16 ----------------
__global__ void split_x(const float* __restrict__ x) {
    size_t i = ((size_t)blockIdx.x * 256 + threadIdx.x) * 8;
    float4 v0 = *(const float4*)(x + i);
    float4 v1 = *(const float4*)(x + i + 4);
    __half h[8] = {__float2half(v0.x), __float2half(v0.y), __float2half(v0.z), __float2half(v0.w),
                   __float2half(v1.x), __float2half(v1.y), __float2half(v1.z), __float2half(v1.w)};
    *(uint4*)(g_xh + i) = *(uint4*)h;
}

// ---------------- W/U prep (merged) + flag init ----------------
// in [k][n] (1024 x 4096). out[n'][k], n' = (j>>3)*32 + gate*8 + (j&7)
__global__ void prep_wu(const float* __restrict__ W, const float* __restrict__ U) {
    __shared__ float tile[32][33];
    const float* in = blockIdx.z ? U : W;
    __half* oh = blockIdx.z ? g_Uh : g_Wh;
    int n0 = blockIdx.x * 32, k0 = blockIdx.y * 32;
    int tx = threadIdx.x, ty = threadIdx.y;
#pragma unroll
    for (int i = 0; i < 4; i++)
        tile[ty + i * 8][tx] = in[(size_t)(k0 + ty + i * 8) * G_ + n0 + tx];
    __syncthreads();
#pragma unroll
    for (int i = 0; i < 4; i++) {
        int n = n0 + ty + i * 8;
        int gate = n >> 10, j = n & 1023;
        int np = ((j >> 3) << 5) + (gate << 3) + (j & 7);
        oh[(size_t)np * 1024 + k0 + tx] = __float2half(tile[tx][ty + i * 8]);
    }
    if (blockIdx.x == 0 && blockIdx.y == 0 && blockIdx.z == 0) {
        int tid = ty * 32 + tx;
        for (int i = tid; i < RBLK * 16; i += 256) g_flag[i] = 0;
    }
}

// ---------------- xW GEMM (fp16 mma, cp.async 3-stage): g_xw[t][n'][b] = x@W + bias ----------------
#define XP 80
#define XB (128 * XP)         // 10240 per stage
#define XBOFF 30720           // B stages base
#define XSM 67584

__global__ __launch_bounds__(256, 2) void gemm_xw_tc(const float* __restrict__ bias) {
    extern __shared__ char sm[];
    uint32_t sb = smem_u32(sm);
    int tid = threadIdx.x, w = tid >> 5, lane = tid & 31;
    int wm = w & 1, wn = w >> 1;
    int n0 = blockIdx.x * 128, m0 = blockIdx.y * 128;

    int r = tid & 127, sel = tid >> 7;
    int mg = m0 + r, bb = mg & 63, tt = mg >> 6;
    const __half* pA  = g_xh + ((size_t)bb * S_ + tt) * D_ + sel * 16;
    const __half* pBh = g_Wh + (size_t)(n0 + r) * D_ + sel * 16;
    uint32_t stOff = (uint32_t)(r * XP + sel * 32);

    uint32_t aoff = (uint32_t)((wm * 64 + (lane & 15)) * XP + (lane >> 4) * 16);
    uint32_t boff = (uint32_t)((wn * 32 + (lane & 15)) * XP + (lane >> 4) * 16);

    float acc[4][4][4];
#pragma unroll
    for (int i = 0; i < 4; i++)
#pragma unroll
        for (int j = 0; j < 4; j++)
#pragma unroll
            for (int q = 0; q < 4; q++) acc[i][j][q] = 0.f;

    auto issue = [&](int c, int s) {
        const __half* a = pA + c * 32;
        const __half* b = pBh + c * 32;
        uint32_t as_ = sb + (uint32_t)s * XB + stOff;
        uint32_t bs_ = sb + XBOFF + (uint32_t)s * XB + stOff;
        cpa16(as_, a);      cpa16(as_ + 16, a + 8);
        cpa16(bs_, b);      cpa16(bs_ + 16, b + 8);
        CP_COMMIT();
    };
    issue(0, 0);
    issue(1, 1);

    for (int c = 0; c < 32; c++) {
        if (c < 30) { CP_WAITN(1); } else { CP_WAITN(0); }
        __syncthreads();
        if (c < 30) issue(c + 2, (c + 2) % 3);
        uint32_t st = (uint32_t)(c % 3);
        uint32_t AH = sb + st * XB, BH = sb + XBOFF + st * XB;
#pragma unroll
        for (int kk = 0; kk < 2; kk++) {
            uint32_t kb = kk * 32;
            uint32_t ah[4][4], bh[4][2], tb[4];
#pragma unroll
            for (int mt = 0; mt < 4; mt++)
                ldm_x4(ah[mt], AH + aoff + mt * 16 * XP + kb);
#pragma unroll
            for (int g2 = 0; g2 < 2; g2++) {
                ldm_x4(tb, BH + boff + g2 * 16 * XP + kb);
                bh[g2 * 2][0] = tb[0]; bh[g2 * 2][1] = tb[2];
                bh[g2 * 2 + 1][0] = tb[1]; bh[g2 * 2 + 1][1] = tb[3];
            }
#pragma unroll
            for (int mt = 0; mt < 4; mt++)
#pragma unroll
                for (int nt = 0; nt < 4; nt++)
                    mma16816(acc[mt][nt], ah[mt], bh[nt]);
        }
    }

    __syncthreads();
    float* stg = (float*)sm;
#pragma unroll
    for (int mt = 0; mt < 4; mt++)
#pragma unroll
        for (int nt = 0; nt < 4; nt++) {
            int m = wm * 64 + mt * 16 + (lane >> 2);
            int nr = wn * 32 + nt * 8 + (lane & 3) * 2;
            stg[nr * 132 + m] = acc[mt][nt][0];
            stg[(nr + 1) * 132 + m] = acc[mt][nt][1];
            stg[nr * 132 + m + 8] = acc[mt][nt][2];
            stg[(nr + 1) * 132 + m + 8] = acc[mt][nt][3];
        }
    __syncthreads();
    int t0 = m0 >> 6;
#pragma unroll
    for (int i = 0; i < 16; i++) {
        int idx = tid + i * 256;
        int nr = idx >> 5, q = idx & 31;
        int np = n0 + nr;
        int gate = (np >> 3) & 3;
        int jo = ((np >> 5) << 3) + (np & 7);
        float bv = __ldg(bias + gate * H_ + jo);
        float4 v = *(float4*)&stg[nr * 132 + q * 4];
        v.x += bv; v.y += bv; v.z += bv; v.w += bv;
        *(float4*)&g_xw[((size_t)(t0 + (q >> 4)) * G_ + np) * 64 + (q & 15) * 4] = v;
    }
}

// ---------------- persistent recurrence: 64 CTAs x 512 thr, 3-stage h ring ----------------
// smem: U[64][2064]=132096 | Hc[3][64][272]=52224 | Gs[64*65 f32]=16640 | XW[4096 f32]=16384
#define UPB 2064
#define HPB 272
#define HOFF 132096
#define HCB 17408
#define GSO 184320
#define RXW 200960
#define RSM 217344

__global__ __launch_bounds__(512, 1) void lstm_recur(float* __restrict__ out,
                                                     float* __restrict__ hT,
                                                     float* __restrict__ cT) {
    extern __shared__ char sm[];
    uint32_t sb = smem_u32(sm);
    int tid = threadIdx.x, w = tid >> 5, lane = tid & 31;
    int wm = w & 1, wn = w >> 1;              // 2m x 8n warp grid; warp tile 32m x 8n, full K
    int jt = blockIdx.x, n0r = jt * 64, j0 = jt * 16;

    // preload resident U tile: 64 n' rows x 1024 k fp16
    {
        int row = tid >> 3, seg = (tid & 7) * 256;
        const __half* ph = g_Uh + (size_t)(n0r + row) * H_ + seg / 2;
        char* dh = sm + row * UPB + seg;
#pragma unroll
        for (int i = 0; i < 16; i++)
            *(uint4*)(dh + i * 16) = *(const uint4*)(ph + i * 8);
    }

    uint32_t aoff = (uint32_t)((wm * 32 + (lane & 15)) * HPB + (lane >> 4) * 16);
    uint32_t boff = (uint32_t)((wn * 8 + (lane & 7)) * UPB + ((lane >> 3) & 1) * 16);
    float* Gs = (float*)(sm + GSO);
    float* XWS = (float*)(sm + RXW);

    // h chunk staging: thread -> rows (tid>>4, tid>>4 + 32), 16B col (tid&15)
    int hrow = tid >> 4, hcol = tid & 15;

    // cell ownership: thread -> (b = eb, j pair jj0), c in registers
    int eb = tid & 63, jg = tid >> 6;   // jg 0..7
    int jj0 = jg * 2;
    float creg0 = 0.f, creg1 = 0.f;
    const unsigned* myflag = &g_flag[(tid & 63) * 16];
    __syncthreads();

    for (int t = 0; t < S_; t++) {
        // issue xw[t] tile (64 n' x 64 b fp32 = 16KB); no dependency — overlaps flag poll
        {
            const float* xwp = g_xw + ((size_t)t * G_ + n0r) * 64 + tid * 8;
            uint32_t d = sb + RXW + (uint32_t)tid * 32;
            cpa16(d, xwp);
            cpa16(d + 16, xwp + 4);
            CP_COMMIT();
        }
        float acc0[4] = {0.f, 0.f, 0.f, 0.f};
        float acc1[4] = {0.f, 0.f, 0.f, 0.f};

        if (t > 0) {
            // dataflow wait: 64 producer flags (one per thread, tid<64)
            if (tid < RBLK) {
                unsigned v;
                do {
                    asm volatile("ld.global.acquire.gpu.u32 %0, [%1];" : "=r"(v) : "l"(myflag) : "memory");
                    if (v < (unsigned)t) __nanosleep(32);
                } while (v < (unsigned)t);
            }
            __syncthreads();
            const __half* hh = g_hh[t & 1];
            auto issue_h = [&](int c) {
                uint32_t buf = sb + HOFF + (uint32_t)(c % 3) * HCB;
                const __half* s0 = hh + (size_t)hrow * H_ + c * 128 + hcol * 8;
                uint32_t d0 = buf + (uint32_t)(hrow * HPB + hcol * 16);
                cpa16(d0, s0);
                cpa16(d0 + 32 * HPB, s0 + 32 * H_);
                CP_COMMIT();
            };
            issue_h(0);
            issue_h(1);
            for (int c = 0; c < 8; c++) {
                // outstanding here: H_c, H_{c+1} (+XW at c=0). wait_group 1 retires through H_c.
                if (c < 7) { CP_WAITN(1); } else { CP_WAITN(0); }
                __syncthreads();   // also: all warps finished chunk c-1 -> buf (c+2)%3 reusable
                if (c < 6) issue_h(c + 2);
                uint32_t AH = sb + HOFF + (uint32_t)(c % 3) * HCB;
                uint32_t BH = sb + (uint32_t)c * 256;
#pragma unroll
                for (int kk = 0; kk < 8; kk++) {
                    uint32_t kb = (uint32_t)kk * 32;
                    uint32_t a0[4], a1[4], b0[2];
                    ldm_x4(a0, AH + aoff + kb);
                    ldm_x4(a1, AH + aoff + 16 * HPB + kb);
                    ldm_x2(b0, BH + boff + kb);
                    mma16816(acc0, a0, b0);
                    mma16816(acc1, a1, b0);
                }
            }
        } else {
            CP_WAITN(0);
            __syncthreads();
        }
        // stage gates: Gs[b][n'_rel], pitch 65 (full-K accumulators, no split-k reduce)
        {
            int rb = wm * 32 + (lane >> 2);
            int cb = wn * 8 + (lane & 3) * 2;
            Gs[rb * 65 + cb]            = acc0[0];
            Gs[rb * 65 + cb + 1]        = acc0[1];
            Gs[(rb + 8) * 65 + cb]      = acc0[2];
            Gs[(rb + 8) * 65 + cb + 1]  = acc0[3];
            Gs[(rb + 16) * 65 + cb]     = acc1[0];
            Gs[(rb + 16) * 65 + cb + 1] = acc1[1];
            Gs[(rb + 24) * 65 + cb]     = acc1[2];
            Gs[(rb + 24) * 65 + cb + 1] = acc1[3];
        }
        __syncthreads();
        // fused cell update: 512 threads x 2 (b,j) pairs; c in registers
        {
            float hv0, hv1;
#pragma unroll
            for (int u = 0; u < 2; u++) {
                int jj = jj0 + u;
                int ci_ = ((jj >> 3) << 5) + (jj & 7);   // gate-0 column in n'-space
                float vi = Gs[eb * 65 + ci_]      + XWS[ci_ * 64 + eb];
                float vf = Gs[eb * 65 + ci_ + 8]  + XWS[(ci_ + 8) * 64 + eb];
                float vg = Gs[eb * 65 + ci_ + 16] + XWS[(ci_ + 16) * 64 + eb];
                float vo = Gs[eb * 65 + ci_ + 24] + XWS[(ci_ + 24) * 64 + eb];
                float& cr = u ? creg1 : creg0;
                cr = fsig(vf) * cr + fsig(vi) * ftanh(vg);
                float hv = fsig(vo) * ftanh(cr);
                if (u) hv1 = hv; else hv0 = hv;
            }
            __half hb2[2] = {__float2half(hv0), __float2half(hv1)};
            *(uint32_t*)&g_hh[(t + 1) & 1][eb * H_ + j0 + jj0] = *(uint32_t*)hb2;
            float* op = out + (size_t)eb * ((size_t)S_ * H_) + (size_t)t * H_ + j0 + jj0;
            *(float2*)op = make_float2(hv0, hv1);
            if (t == S_ - 1 && cT != nullptr) {
                *(float2*)&hT[eb * H_ + j0 + jj0] = make_float2(hv0, hv1);
                *(float2*)&cT[eb * H_ + j0 + jj0] = make_float2(creg0, creg1);
            }
        }
        // publish h(t+1)
        __syncthreads();
        if (t < S_ - 1 && tid == 0) {
            __threadfence();
            asm volatile("st.global.relaxed.gpu.u32 [%0], %1;"
                         :: "l"(&g_flag[jt * 16]), "r"((unsigned)(t + 1)) : "memory");
        }
    }
}

// ---------------- launch ----------------
extern "C" void kernel_launch(void* const* d_in, const int* in_sizes, int n_in,
                              void* d_out, int out_size) {
    const float* x    = (const float*)d_in[0];
    const float* W    = (const float*)d_in[1];
    const float* U    = (const float*)d_in[2];
    const float* bias = (const float*)d_in[3];
    float* out = (float*)d_out;

    float* hT = nullptr;
    float* cT = nullptr;
    long long need = (long long)B_ * S_ * H_ + 2LL * B_ * H_;
    if ((long long)out_size >= need) {
        hT = out + (size_t)B_ * S_ * H_;
        cT = hT + (size_t)B_ * H_;
    }

    cudaFuncSetAttribute(gemm_xw_tc, cudaFuncAttributeMaxDynamicSharedMemorySize, XSM);
    cudaFuncSetAttribute(lstm_recur, cudaFuncAttributeMaxDynamicSharedMemorySize, RSM);

    // launch order: lstm_recur at index 3 (ncu capture slot)
    split_x<<<(B_ * S_ * D_) / (256 * 8), 256>>>(x);                  // 0
    prep_wu<<<dim3(128, 32, 2), dim3(32, 8)>>>(W, U);                 // 1
    gemm_xw_tc<<<dim3(32, 256), 256, XSM>>>(bias);                    // 2
    lstm_recur<<<RBLK, 512, RSM>>>(out, hT, cT);                      // 3
}

// round 15
// speedup vs baseline: 1.3578x; 1.3578x over previous
#include <cuda_runtime.h>
#include <cuda_fp16.h>
#include <cstdint>
#include <cmath>

#define B_ 64
#define S_ 512
#define D_ 1024
#define H_ 1024
#define G_ 4096
#define RBLK 128

__device__ __half g_xh[(size_t)B_ * S_ * D_];   // x fp16 [b][s][d]
__device__ __half g_Wh[(size_t)G_ * D_];        // W^T perm [n'][k]
__device__ __half g_Uh[(size_t)G_ * H_];        // U^T perm [n'][k]
__device__ __half g_hh[2][B_ * H_];             // h fp16 [b][j], dbl buf
__device__ unsigned g_flag[RBLK * 16];          // per-CTA monotonic step flags

__device__ __forceinline__ uint32_t smem_u32(const void* p) {
    uint32_t a;
    asm("{ .reg .u64 t; cvta.to.shared.u64 t, %1; cvt.u32.u64 %0, t; }" : "=r"(a) : "l"(p));
    return a;
}
__device__ __forceinline__ void ldm_x4(uint32_t* r, uint32_t a) {
    asm volatile("ldmatrix.sync.aligned.m8n8.x4.shared.b16 {%0,%1,%2,%3}, [%4];"
                 : "=r"(r[0]), "=r"(r[1]), "=r"(r[2]), "=r"(r[3]) : "r"(a));
}
__device__ __forceinline__ void mma16816(float* d, const uint32_t* a, const uint32_t* b) {
    asm volatile("mma.sync.aligned.m16n8k16.row.col.f32.f16.f16.f32 "
                 "{%0,%1,%2,%3},{%4,%5,%6,%7},{%8,%9},{%0,%1,%2,%3};"
                 : "+f"(d[0]), "+f"(d[1]), "+f"(d[2]), "+f"(d[3])
                 : "r"(a[0]), "r"(a[1]), "r"(a[2]), "r"(a[3]), "r"(b[0]), "r"(b[1]));
}
__device__ __forceinline__ void cpa16(uint32_t dst, const void* src) {
    asm volatile("cp.async.cg.shared.global [%0], [%1], 16;" :: "r"(dst), "l"(src));
}
#define CP_COMMIT() asm volatile("cp.async.commit_group;" ::: "memory")
#define CP_WAITN(n) asm volatile("cp.async.wait_group %0;" :: "n"(n) : "memory")
__device__ __forceinline__ float fsig(float x) {
    return __fdividef(1.f, 1.f + __expf(-x));
}
__device__ __forceinline__ float ftanh(float x) {
    x = fminf(fmaxf(x, -15.f), 15.f);
    float e = __expf(2.f * x);
    return __fdividef(e - 1.f, e + 1.f);
}

__global__ void split_x(const float* __restrict__ x) {
    size_t i = ((size_t)blockIdx.x * 256 + threadIdx.x) * 8;
    float4 v0 = *(const float4*)(x + i);
    float4 v1 = *(const float4*)(x + i + 4);
    __half h[8] = {__float2half(v0.x), __float2half(v0.y), __float2half(v0.z), __float2half(v0.w),
                   __float2half(v1.x), __float2half(v1.y), __float2half(v1.z), __float2half(v1.w)};
    *(uint4*)(g_xh + i) = *(uint4*)h;
}

// W/U prep: in [k][n] -> out[n'][k] fp16, n' = (j>>3)*32 + gate*8 + (j&7); + flag init
__global__ void prep_wu(const float* __restrict__ W, const float* __restrict__ U) {
    __shared__ float tile[32][33];
    const float* in = blockIdx.z ? U : W;
    __half* oh = blockIdx.z ? g_Uh : g_Wh;
    int n0 = blockIdx.x * 32, k0 = blockIdx.y * 32;
    int tx = threadIdx.x, ty = threadIdx.y;
#pragma unroll
    for (int i = 0; i < 4; i++)
        tile[ty + i * 8][tx] = in[(size_t)(k0 + ty + i * 8) * G_ + n0 + tx];
    __syncthreads();
#pragma unroll
    for (int i = 0; i < 4; i++) {
        int n = n0 + ty + i * 8;
        int gate = n >> 10, j = n & 1023;
        int np = ((j >> 3) << 5) + (gate << 3) + (j & 7);
        oh[(size_t)np * 1024 + k0 + tx] = __float2half(tile[tx][ty + i * 8]);
    }
    if (blockIdx.x == 0 && blockIdx.y == 0 && blockIdx.z == 0) {
        int tid = ty * 32 + tx;
        for (int i = tid; i < RBLK * 16; i += 256) g_flag[i] = 0;
    }
}

// fused persistent recurrence: gates(t) = [x_t | h_t] @ [Wtile; Utile] + bias (K=2048)
// smem: W[32][2064] | U[32][2064] | A[2][64][528] | Gk0[64*33 f32] | Gk1 | bias_s[32]
#define UPB 2064
#define APB 528
#define UOFF 66048
#define AOFF 132096
#define ABUF 33792
#define GS0O 199680
#define GS1O 208128
#define BIASO 216576
#define RSM 216704

__global__ __launch_bounds__(256, 1) void lstm_recur(float* __restrict__ out,
                                                     float* __restrict__ hT,
                                                     float* __restrict__ cT,
                                                     const float* __restrict__ bias) {
    extern __shared__ char sm[];
    uint32_t sb = smem_u32(sm);
    int tid = threadIdx.x, w = tid >> 5, lane = tid & 31;
    int wm = w & 1, wn = (w >> 1) & 1, kg = w >> 2;   // 2m x 2n x 2kg warp grid
    int jt = blockIdx.x, n0r = jt * 32, j0 = jt * 8;

    { // resident W + U tiles (32 n' rows x 1024 k each)
        int row = tid >> 3, kb = (tid & 7) * 128;
        const __half* pw = g_Wh + (size_t)(n0r + row) * H_ + kb;
        const __half* pu = g_Uh + (size_t)(n0r + row) * H_ + kb;
        char* dw = sm + row * UPB + kb * 2;
        char* du = sm + UOFF + row * UPB + kb * 2;
#pragma unroll
        for (int i = 0; i < 16; i++) {
            *(uint4*)(dw + i * 16) = *(const uint4*)(pw + i * 8);
            *(uint4*)(du + i * 16) = *(const uint4*)(pu + i * 8);
        }
    }
    if (tid < 32) {   // permuted bias table
        int np = n0r + tid;
        int gate = (np >> 3) & 3;
        int jo = ((np >> 5) << 3) + (np & 7);
        ((float*)(sm + BIASO))[tid] = bias[gate * H_ + jo];
    }

    // ldmatrix bases: A rows = batch, B rows = n'; kg picks 128-k half of each 256-k chunk
    uint32_t aoff = (uint32_t)((wm * 32 + (lane & 15)) * APB + (lane >> 4) * 16 + kg * 256);
    uint32_t boff = (uint32_t)((wn * 16 + (lane & 15)) * UPB + (lane >> 4) * 16 + kg * 256);
    float* Gk = (float*)(sm + GS0O + kg * 8448);
    float* Gs0 = (float*)(sm + GS0O);
    float* Gs1 = (float*)(sm + GS1O);
    float* bias_s = (float*)(sm + BIASO);

    int arow = tid >> 5, aseg = tid & 31;        // A staging: 8 rows/thread, 16B seg
    int eb = tid & 63, jg = tid >> 6, jj0 = jg * 2;
    float creg0 = 0.f, creg1 = 0.f;
    const unsigned* myflag = &g_flag[(tid & 127) * 16];
    __syncthreads();

    for (int t = 0; t < S_; t++) {
        // chunk ci: 0..3 = x_t vs W (k = ci*256..), 4..7 = h_t vs U
        auto issue_c = [&](int ci) {
            uint32_t buf = sb + AOFF + (uint32_t)(ci & 1) * ABUF;
            int klo = (ci & 3) * 256;
#pragma unroll
            for (int i = 0; i < 8; i++) {
                int row = arow + i * 8;
                const __half* s = (ci < 4)
                    ? g_xh + ((size_t)row * S_ + t) * D_ + klo + aseg * 8
                    : g_hh[t & 1] + (size_t)row * H_ + klo + aseg * 8;
                cpa16(buf + (uint32_t)(row * APB + aseg * 16), s);
            }
            CP_COMMIT();
        };

        int nch = (t > 0) ? 8 : 4;
        issue_c(0);                              // x chunks: always ready
        issue_c(1);
        if (t > 0 && tid < RBLK) {               // dataflow wait for h(t) producers
            unsigned v;
            do {
                asm volatile("ld.global.acquire.gpu.u32 %0, [%1];" : "=r"(v) : "l"(myflag) : "memory");
                if (v < (unsigned)t) __nanosleep(32);
            } while (v < (unsigned)t);
        }

        // R11-proven accumulator layout: acc[mt][nt], mt = 16-row half, nt = 8-col half
        float acc[2][2][4];
#pragma unroll
        for (int i = 0; i < 2; i++)
#pragma unroll
            for (int j = 0; j < 2; j++)
#pragma unroll
                for (int q = 0; q < 4; q++) acc[i][j][q] = 0.f;

        for (int c = 0; c < nch; c++) {
            // outstanding groups: {c, c+1} (c+1 if issued) -> wait 1 retires chunk c
            if (c < nch - 1) { CP_WAITN(1); } else { CP_WAITN(0); }
            __syncthreads();
            uint32_t AH = sb + AOFF + (uint32_t)(c & 1) * ABUF;
            uint32_t BH = sb + ((c < 4) ? 0u : (uint32_t)UOFF) + (uint32_t)(c & 3) * 512;
#pragma unroll
            for (int kk = 0; kk < 8; kk++) {
                uint32_t kb = (uint32_t)kk * 32;
                uint32_t a0[4], a1[4], tb[4], b0[2], b1[2];
                ldm_x4(a0, AH + aoff + kb);                 // rows wm*32 .. +15
                ldm_x4(a1, AH + aoff + 16 * APB + kb);      // rows wm*32+16 .. +31
                ldm_x4(tb, BH + boff + kb);
                b0[0] = tb[0]; b0[1] = tb[2];               // cols wn*16 .. +7
                b1[0] = tb[1]; b1[1] = tb[3];               // cols wn*16+8 .. +15
                mma16816(acc[0][0], a0, b0);
                mma16816(acc[0][1], a0, b1);
                mma16816(acc[1][0], a1, b0);
                mma16816(acc[1][1], a1, b1);
            }
            if (c + 2 < nch) {
                __syncthreads();                 // all warps done reading buf (c&1)
                issue_c(c + 2);                  // refill it with chunk c+2
            }
        }

        // stage split-kg partial gates (verbatim R11 store)
        {
            int rb = wm * 32 + (lane >> 2);
            int cb = wn * 16 + (lane & 3) * 2;
#pragma unroll
            for (int mt = 0; mt < 2; mt++)
#pragma unroll
                for (int nt = 0; nt < 2; nt++) {
                    int rr2 = rb + mt * 16, cc2 = cb + nt * 8;
                    Gk[rr2 * 33 + cc2]           = acc[mt][nt][0];
                    Gk[rr2 * 33 + cc2 + 1]       = acc[mt][nt][1];
                    Gk[(rr2 + 8) * 33 + cc2]     = acc[mt][nt][2];
                    Gk[(rr2 + 8) * 33 + cc2 + 1] = acc[mt][nt][3];
                }
        }
        __syncthreads();
        // fused cell update (c in registers; bias added here)
        {
            float hv0, hv1;
#pragma unroll
            for (int u = 0; u < 2; u++) {
                int jj = jj0 + u;
                float vi = Gs0[eb * 33 + jj]      + Gs1[eb * 33 + jj]      + bias_s[jj];
                float vf = Gs0[eb * 33 + 8 + jj]  + Gs1[eb * 33 + 8 + jj]  + bias_s[8 + jj];
                float vg = Gs0[eb * 33 + 16 + jj] + Gs1[eb * 33 + 16 + jj] + bias_s[16 + jj];
                float vo = Gs0[eb * 33 + 24 + jj] + Gs1[eb * 33 + 24 + jj] + bias_s[24 + jj];
                float& cr = u ? creg1 : creg0;
                cr = fsig(vf) * cr + fsig(vi) * ftanh(vg);
                float hv = fsig(vo) * ftanh(cr);
                if (u) hv1 = hv; else hv0 = hv;
            }
            __half hb2[2] = {__float2half(hv0), __float2half(hv1)};
            *(uint32_t*)&g_hh[(t + 1) & 1][eb * H_ + j0 + jj0] = *(uint32_t*)hb2;
            float* op = out + (size_t)eb * ((size_t)S_ * H_) + (size_t)t * H_ + j0 + jj0;
            *(float2*)op = make_float2(hv0, hv1);
            if (t == S_ - 1 && cT != nullptr) {
                *(float2*)&hT[eb * H_ + j0 + jj0] = make_float2(hv0, hv1);
                *(float2*)&cT[eb * H_ + j0 + jj0] = make_float2(creg0, creg1);
            }
        }
        // publish h(t+1)
        __syncthreads();
        if (t < S_ - 1 && tid == 0) {
            __threadfence();
            asm volatile("st.global.relaxed.gpu.u32 [%0], %1;"
                         :: "l"(&g_flag[jt * 16]), "r"((unsigned)(t + 1)) : "memory");
        }
    }
}

extern "C" void kernel_launch(void* const* d_in, const int* in_sizes, int n_in,
                              void* d_out, int out_size) {
    const float* x    = (const float*)d_in[0];
    const float* W    = (const float*)d_in[1];
    const float* U    = (const float*)d_in[2];
    const float* bias = (const float*)d_in[3];
    float* out = (float*)d_out;

    float* hT = nullptr;
    float* cT = nullptr;
    long long need = (long long)B_ * S_ * H_ + 2LL * B_ * H_;
    if ((long long)out_size >= need) {
        hT = out + (size_t)B_ * S_ * H_;
        cT = hT + (size_t)B_ * H_;
    }

    cudaFuncSetAttribute(lstm_recur, cudaFuncAttributeMaxDynamicSharedMemorySize, RSM);

    split_x<<<(B_ * S_ * D_) / (256 * 8), 256>>>(x);
    prep_wu<<<dim3(128, 32, 2), dim3(32, 8)>>>(W, U);
    lstm_recur<<<RBLK, 256, RSM>>>(out, hT, cT, bias);
}

// round 16
// speedup vs baseline: 1.5085x; 1.1110x over previous
#include <cuda_runtime.h>
#include <cuda_fp16.h>
#include <cstdint>
#include <cmath>

#define B_ 64
#define S_ 512
#define D_ 1024
#define H_ 1024
#define G_ 4096
#define RBLK 128

// ---------------- scratch (device globals) ----------------
__device__ float g_xw[(size_t)S_ * G_ * B_];    // [t][n'(perm)][b] fp32
__device__ __half g_xh[(size_t)B_ * S_ * D_];   // x fp16
__device__ __half g_Wh[(size_t)G_ * D_];        // W^T perm [n'][k] fp16
__device__ __half g_Uh[(size_t)G_ * H_];        // U^T perm [n'][k] fp16
__device__ __half g_hh[2][B_ * H_];             // h fp16 [b][j], dbl buf
__device__ unsigned g_flag[RBLK * 16];          // per-CTA monotonic step flags

// ---------------- helpers ----------------
__device__ __forceinline__ uint32_t smem_u32(const void* p) {
    uint32_t a;
    asm("{ .reg .u64 t; cvta.to.shared.u64 t, %1; cvt.u32.u64 %0, t; }" : "=r"(a) : "l"(p));
    return a;
}
__device__ __forceinline__ void ldm_x4(uint32_t* r, uint32_t a) {
    asm volatile("ldmatrix.sync.aligned.m8n8.x4.shared.b16 {%0,%1,%2,%3}, [%4];"
                 : "=r"(r[0]), "=r"(r[1]), "=r"(r[2]), "=r"(r[3]) : "r"(a));
}
__device__ __forceinline__ void ldm_x2(uint32_t* r, uint32_t a) {
    asm volatile("ldmatrix.sync.aligned.m8n8.x2.shared.b16 {%0,%1}, [%2];"
                 : "=r"(r[0]), "=r"(r[1]) : "r"(a));
}
__device__ __forceinline__ void mma16816(float* d, const uint32_t* a, const uint32_t* b) {
    asm volatile("mma.sync.aligned.m16n8k16.row.col.f32.f16.f16.f32 "
                 "{%0,%1,%2,%3},{%4,%5,%6,%7},{%8,%9},{%0,%1,%2,%3};"
                 : "+f"(d[0]), "+f"(d[1]), "+f"(d[2]), "+f"(d[3])
                 : "r"(a[0]), "r"(a[1]), "r"(a[2]), "r"(a[3]), "r"(b[0]), "r"(b[1]));
}
__device__ __forceinline__ void cpa16(uint32_t dst, const void* src) {
    asm volatile("cp.async.cg.shared.global [%0], [%1], 16;" :: "r"(dst), "l"(src));
}
#define CP_COMMIT() asm volatile("cp.async.commit_group;" ::: "memory")
#define CP_WAITN(n) asm volatile("cp.async.wait_group %0;" :: "n"(n) : "memory")
__device__ __forceinline__ float fsig(float x) {
    return __fdividef(1.f, 1.f + __expf(-x));
}
__device__ __forceinline__ float ftanh(float x) {
    x = fminf(fmaxf(x, -15.f), 15.f);
    float e = __expf(2.f * x);
    return __fdividef(e - 1.f, e + 1.f);
}

// ---------------- x: fp32 -> fp16 ----------------
__global__ void split_x(const float* __restrict__ x) {
    size_t i = ((size_t)blockIdx.x * 256 + threadIdx.x) * 8;
    float4 v0 = *(const float4*)(x + i);
    float4 v1 = *(const float4*)(x + i + 4);
    __half h[8] = {__float2half(v0.x), __float2half(v0.y), __float2half(v0.z), __float2half(v0.w),
                   __float2half(v1.x), __float2half(v1.y), __float2half(v1.z), __float2half(v1.w)};
    *(uint4*)(g_xh + i) = *(uint4*)h;
}

// ---------------- W/U prep (merged) + flag init ----------------
// in [k][n] (1024 x 4096). out[n'][k], n' = (j>>3)*32 + gate*8 + (j&7)
__global__ void prep_wu(const float* __restrict__ W, const float* __restrict__ U) {
    __shared__ float tile[32][33];
    const float* in = blockIdx.z ? U : W;
    __half* oh = blockIdx.z ? g_Uh : g_Wh;
    int n0 = blockIdx.x * 32, k0 = blockIdx.y * 32;
    int tx = threadIdx.x, ty = threadIdx.y;
#pragma unroll
    for (int i = 0; i < 4; i++)
        tile[ty + i * 8][tx] = in[(size_t)(k0 + ty + i * 8) * G_ + n0 + tx];
    __syncthreads();
#pragma unroll
    for (int i = 0; i < 4; i++) {
        int n = n0 + ty + i * 8;
        int gate = n >> 10, j = n & 1023;
        int np = ((j >> 3) << 5) + (gate << 3) + (j & 7);
        oh[(size_t)np * 1024 + k0 + tx] = __float2half(tile[tx][ty + i * 8]);
    }
    if (blockIdx.x == 0 && blockIdx.y == 0 && blockIdx.z == 0) {
        int tid = ty * 32 + tx;
        for (int i = tid; i < RBLK * 16; i += 256) g_flag[i] = 0;
    }
}

// ---------------- xW GEMM: 4 warps, 64x64 warp tiles, cp.async 3-stage ----------------
#define XP 80
#define XB (128 * XP)         // 10240 per stage
#define XBOFF 30720           // B stages base
#define XSM 67584             // >= 61440 stages; >= 67584 epilogue staging

__global__ __launch_bounds__(128, 2) void gemm_xw_tc(const float* __restrict__ bias) {
    extern __shared__ char sm[];
    uint32_t sb = smem_u32(sm);
    int tid = threadIdx.x, w = tid >> 5, lane = tid & 31;
    int wm = w & 1, wn = w >> 1;              // 2m x 2n warp grid; warp tile 64x64
    int n0 = blockIdx.x * 128, m0 = blockIdx.y * 128;

    // staging: thread -> full 64B row segment of chunk
    int r = tid;                              // 0..127
    int mg = m0 + r, bb = mg & 63, tt = mg >> 6;
    const __half* pA = g_xh + ((size_t)bb * S_ + tt) * D_;
    const __half* pB = g_Wh + (size_t)(n0 + r) * D_;
    uint32_t stOff = (uint32_t)(r * XP);

    uint32_t aoff = (uint32_t)((wm * 64 + (lane & 15)) * XP + (lane >> 4) * 16);
    uint32_t boff = (uint32_t)((wn * 64 + (lane & 15)) * XP + (lane >> 4) * 16);

    float acc[4][8][4];
#pragma unroll
    for (int i = 0; i < 4; i++)
#pragma unroll
        for (int j = 0; j < 8; j++)
#pragma unroll
            for (int q = 0; q < 4; q++) acc[i][j][q] = 0.f;

    auto issue = [&](int c, int s) {
        const __half* a = pA + c * 32;
        const __half* b = pB + c * 32;
        uint32_t as_ = sb + (uint32_t)s * XB + stOff;
        uint32_t bs_ = sb + XBOFF + (uint32_t)s * XB + stOff;
#pragma unroll
        for (int q = 0; q < 4; q++) {
            cpa16(as_ + q * 16, a + q * 8);
            cpa16(bs_ + q * 16, b + q * 8);
        }
        CP_COMMIT();
    };
    issue(0, 0);
    issue(1, 1);

    for (int c = 0; c < 32; c++) {
        if (c < 30) { CP_WAITN(1); } else { CP_WAITN(0); }
        __syncthreads();
        if (c < 30) issue(c + 2, (c + 2) % 3);
        uint32_t st = (uint32_t)(c % 3);
        uint32_t AH = sb + st * XB, BH = sb + XBOFF + st * XB;
#pragma unroll
        for (int kk = 0; kk < 2; kk++) {
            uint32_t kb = kk * 32;
            uint32_t ah[4][4], bh[8][2], tb[4];
#pragma unroll
            for (int mt = 0; mt < 4; mt++)
                ldm_x4(ah[mt], AH + aoff + mt * 16 * XP + kb);
#pragma unroll
            for (int g2 = 0; g2 < 4; g2++) {
                ldm_x4(tb, BH + boff + g2 * 16 * XP + kb);
                bh[g2 * 2][0] = tb[0]; bh[g2 * 2][1] = tb[2];
                bh[g2 * 2 + 1][0] = tb[1]; bh[g2 * 2 + 1][1] = tb[3];
            }
#pragma unroll
            for (int mt = 0; mt < 4; mt++)
#pragma unroll
                for (int nt = 0; nt < 8; nt++)
                    mma16816(acc[mt][nt], ah[mt], bh[nt]);
        }
    }

    // epilogue: stage [n_rel][m] fp32 pitch 132, then coalesced write
    __syncthreads();
    float* stg = (float*)sm;
#pragma unroll
    for (int mt = 0; mt < 4; mt++)
#pragma unroll
        for (int nt = 0; nt < 8; nt++) {
            int m = wm * 64 + mt * 16 + (lane >> 2);
            int nr = wn * 64 + nt * 8 + (lane & 3) * 2;
            stg[nr * 132 + m] = acc[mt][nt][0];
            stg[(nr + 1) * 132 + m] = acc[mt][nt][1];
            stg[nr * 132 + m + 8] = acc[mt][nt][2];
            stg[(nr + 1) * 132 + m + 8] = acc[mt][nt][3];
        }
    __syncthreads();
    int t0 = m0 >> 6;
#pragma unroll
    for (int i = 0; i < 32; i++) {
        int idx = tid + i * 128;
        int nr = idx >> 5, q = idx & 31;
        int np = n0 + nr;
        int gate = (np >> 3) & 3;
        int jo = ((np >> 5) << 3) + (np & 7);
        float bv = __ldg(bias + gate * H_ + jo);
        float4 v = *(float4*)&stg[nr * 132 + q * 4];
        v.x += bv; v.y += bv; v.z += bv; v.w += bv;
        *(float4*)&g_xw[((size_t)(t0 + (q >> 4)) * G_ + np) * 64 + (q & 15) * 4] = v;
    }
}

// ---------------- persistent recurrence (verbatim R11 winner) ----------------
// smem: U[32][2064] | H[64][2064] | GS0[64*33 f32] | GS1 | XW[2048 f32]
#define UPB 2064
#define HOFF 66048
#define GS0 198144
#define GS1 206592
#define RXW 215040
#define RSM 223232

__global__ __launch_bounds__(256, 1) void lstm_recur(float* __restrict__ out,
                                                     float* __restrict__ hT,
                                                     float* __restrict__ cT) {
    extern __shared__ char sm[];
    uint32_t sb = smem_u32(sm);
    int tid = threadIdx.x, w = tid >> 5, lane = tid & 31;
    int wm = w & 1, wn = (w >> 1) & 1, kg = w >> 2;   // 2m x 2n x 2k warp grid
    int jt = blockIdx.x, n0r = jt * 32, j0 = jt * 8;

    // preload resident U tile: 32 n' rows x 1024 k fp16
    {
        int row = tid >> 3, kb = (tid & 7) * 128;
        const __half* ph = g_Uh + (size_t)(n0r + row) * H_ + kb;
        char* dh = sm + row * UPB + kb * 2;
#pragma unroll
        for (int i = 0; i < 16; i++)
            *(uint4*)(dh + i * 16) = *(const uint4*)(ph + i * 8);
    }

    uint32_t abase = sb + HOFF + (uint32_t)((wm * 32 + (lane & 15)) * UPB + (lane >> 4) * 16 + kg * 512);
    uint32_t bbase = sb + (uint32_t)((wn * 16 + (lane & 15)) * UPB + (lane >> 4) * 16 + kg * 512);
    float* XWS = (float*)(sm + RXW);
    float* Gk = (float*)(sm + GS0 + kg * 8448);
    float* Gs0 = (float*)(sm + GS0);
    float* Gs1 = (float*)(sm + GS1);

    int eb = tid & 63, jj0 = (tid >> 6) * 2;
    float creg0 = 0.f, creg1 = 0.f;
    const unsigned* myflag = &g_flag[(tid & 127) * 16];
    __syncthreads();

    for (int t = 0; t < S_; t++) {
        // issue xw[t] tile via cp.async (no dependency — overlaps flag polling)
        {
            const float* xwp = g_xw + ((size_t)t * G_ + n0r) * 64 + tid * 8;
            uint32_t d = sb + RXW + (uint32_t)tid * 32;
            cpa16(d, xwp);
            cpa16(d + 16, xwp + 4);
            CP_COMMIT();
        }
        if (t > 0) {
            // dataflow wait: h(t) published by all producers (128 flags, 1/thread)
            if (tid < RBLK) {
                unsigned v;
                do {
                    asm volatile("ld.global.acquire.gpu.u32 %0, [%1];" : "=r"(v) : "l"(myflag) : "memory");
                    if (v < (unsigned)t) __nanosleep(32);
                } while (v < (unsigned)t);
            }
            __syncthreads();
            const __half* hh = g_hh[t & 1];
            // chunk0 (k 0..511)
#pragma unroll
            for (int j = 0; j < 8; j++) {
                int row = j * 8 + w;
                const __half* src = hh + (size_t)row * H_ + lane * 8;
                uint32_t dst = sb + HOFF + (uint32_t)(row * UPB + lane * 16);
                cpa16(dst, src);
                cpa16(dst + 512, src + 256);
            }
            CP_COMMIT();
            // chunk1 (k 512..1023)
#pragma unroll
            for (int j = 0; j < 8; j++) {
                int row = j * 8 + w;
                const __half* src = hh + (size_t)row * H_ + lane * 8;
                uint32_t dst = sb + HOFF + (uint32_t)(row * UPB + lane * 16);
                cpa16(dst + 1024, src + 512);
                cpa16(dst + 1536, src + 768);
            }
            CP_COMMIT();
        }

        float acc[2][2][4];
#pragma unroll
        for (int i = 0; i < 2; i++)
#pragma unroll
            for (int j = 0; j < 2; j++)
#pragma unroll
                for (int q = 0; q < 4; q++) acc[i][j][q] = 0.f;

        if (t > 0) {
            CP_WAITN(1);           // xw + chunk0 complete; chunk1 in flight
            __syncthreads();
#pragma unroll 8
            for (int kk = 0; kk < 16; kk++) {
                uint32_t kb = (uint32_t)kk * 32;
                uint32_t a0[4], a1[4], tb[4], b0[2], b1[2];
                ldm_x4(a0, abase + kb);
                ldm_x4(a1, abase + 16 * UPB + kb);
                ldm_x4(tb, bbase + kb);
                b0[0] = tb[0]; b0[1] = tb[2];
                b1[0] = tb[1]; b1[1] = tb[3];
                mma16816(acc[0][0], a0, b0);
                mma16816(acc[0][1], a0, b1);
                mma16816(acc[1][0], a1, b0);
                mma16816(acc[1][1], a1, b1);
            }
            CP_WAITN(0);           // chunk1 complete
            __syncthreads();
#pragma unroll 8
            for (int kk = 0; kk < 16; kk++) {
                uint32_t kb = 1024u + (uint32_t)kk * 32;
                uint32_t a0[4], a1[4], tb[4], b0[2], b1[2];
                ldm_x4(a0, abase + kb);
                ldm_x4(a1, abase + 16 * UPB + kb);
                ldm_x4(tb, bbase + kb);
                b0[0] = tb[0]; b0[1] = tb[2];
                b1[0] = tb[1]; b1[1] = tb[3];
                mma16816(acc[0][0], a0, b0);
                mma16816(acc[0][1], a0, b1);
                mma16816(acc[1][0], a1, b0);
                mma16816(acc[1][1], a1, b1);
            }
        } else {
            CP_WAITN(0);
            __syncthreads();
        }
        // stage split-k partial gates
        {
            int rb = wm * 32 + (lane >> 2);
            int cb = wn * 16 + (lane & 3) * 2;
#pragma unroll
            for (int mt = 0; mt < 2; mt++)
#pragma unroll
                for (int nt = 0; nt < 2; nt++) {
                    int rr2 = rb + mt * 16, cc2 = cb + nt * 8;
                    Gk[rr2 * 33 + cc2]           = acc[mt][nt][0];
                    Gk[rr2 * 33 + cc2 + 1]       = acc[mt][nt][1];
                    Gk[(rr2 + 8) * 33 + cc2]     = acc[mt][nt][2];
                    Gk[(rr2 + 8) * 33 + cc2 + 1] = acc[mt][nt][3];
                }
        }
        __syncthreads();
        // fused cell update (c in registers, fast transcendentals)
        {
            float hv0, hv1;
#pragma unroll
            for (int u = 0; u < 2; u++) {
                int jj = jj0 + u;
                float vi = Gs0[eb * 33 + jj]      + Gs1[eb * 33 + jj]      + XWS[jj * 64 + eb];
                float vf = Gs0[eb * 33 + 8 + jj]  + Gs1[eb * 33 + 8 + jj]  + XWS[(8 + jj) * 64 + eb];
                float vg = Gs0[eb * 33 + 16 + jj] + Gs1[eb * 33 + 16 + jj] + XWS[(16 + jj) * 64 + eb];
                float vo = Gs0[eb * 33 + 24 + jj] + Gs1[eb * 33 + 24 + jj] + XWS[(24 + jj) * 64 + eb];
                float& cr = u ? creg1 : creg0;
                cr = fsig(vf) * cr + fsig(vi) * ftanh(vg);
                float hv = fsig(vo) * ftanh(cr);
                if (u) hv1 = hv; else hv0 = hv;
            }
            __half hb2[2] = {__float2half(hv0), __float2half(hv1)};
            *(uint32_t*)&g_hh[(t + 1) & 1][eb * H_ + j0 + jj0] = *(uint32_t*)hb2;
            float* op = out + (size_t)eb * ((size_t)S_ * H_) + (size_t)t * H_ + j0 + jj0;
            *(float2*)op = make_float2(hv0, hv1);
            if (t == S_ - 1 && cT != nullptr) {
                *(float2*)&hT[eb * H_ + j0 + jj0] = make_float2(hv0, hv1);
                *(float2*)&cT[eb * H_ + j0 + jj0] = make_float2(creg0, creg1);
            }
        }
        // publish h(t+1)
        __syncthreads();
        if (t < S_ - 1 && tid == 0) {
            __threadfence();
            asm volatile("st.global.relaxed.gpu.u32 [%0], %1;"
                         :: "l"(&g_flag[jt * 16]), "r"((unsigned)(t + 1)) : "memory");
        }
    }
}

// ---------------- launch ----------------
extern "C" void kernel_launch(void* const* d_in, const int* in_sizes, int n_in,
                              void* d_out, int out_size) {
    const float* x    = (const float*)d_in[0];
    const float* W    = (const float*)d_in[1];
    const float* U    = (const float*)d_in[2];
    const float* bias = (const float*)d_in[3];
    float* out = (float*)d_out;

    float* hT = nullptr;
    float* cT = nullptr;
    long long need = (long long)B_ * S_ * H_ + 2LL * B_ * H_;
    if ((long long)out_size >= need) {
        hT = out + (size_t)B_ * S_ * H_;
        cT = hT + (size_t)B_ * H_;
    }

    cudaFuncSetAttribute(gemm_xw_tc, cudaFuncAttributeMaxDynamicSharedMemorySize, XSM);
    cudaFuncSetAttribute(lstm_recur, cudaFuncAttributeMaxDynamicSharedMemorySize, RSM);

    // launch order: gemm at index 2, lstm_recur at index 3 (ncu capture slot)
    split_x<<<(B_ * S_ * D_) / (256 * 8), 256>>>(x);                  // 0
    prep_wu<<<dim3(128, 32, 2), dim3(32, 8)>>>(W, U);                 // 1
    gemm_xw_tc<<<dim3(32, 256), 128, XSM>>>(bias);                    // 2
    lstm_recur<<<RBLK, 256, RSM>>>(out, hT, cT);                      // 3
}